// round 14
// baseline (speedup 1.0000x reference)
#include <cuda_runtime.h>
#include <cuda_bf16.h>
#include <math.h>

#define NPTS 16384
#define KNN  16
#define G    12
#define GC   (G * G * G)     // 1728 cells, ~9.5 pts/cell
#define HCELL (1.0f / G)
#define FULLM 0xffffffffu
typedef unsigned long long ull;

// ---------------- scratch (device globals, no allocations) ----------------
__device__ float4 d_pts4[NPTS];
__device__ float  d_T7v[104 * 32 * 4];   // (c4, j, q) <- finw[j][4*c4+q]
__device__ float  d_cf[NPTS * 128];      // indexed by SORTED position
__device__ float  d_g [NPTS * 128];      // indexed by SORTED position
__device__ float  d_h [NPTS * 128];      // indexed by SORTED position
__device__ int    d_knn[NPTS * KNN];     // [sorted query][k] -> sorted neighbor pos
__device__ float  d_wgt[NPTS * KNN];     // [sorted query][k]
__device__ int    d_cellStart[GC + 1];
__device__ int    d_ptCell[NPTS];
__device__ float4 d_spts[NPTS];
__device__ int    d_sidx[NPTS];          // sorted pos -> original index
__device__ int    d_rank[NPTS];          // original index -> sorted pos

__device__ __forceinline__ float lrelu(float x) { return x > 0.f ? x : 0.01f * x; }

__device__ __forceinline__ ull pack2(float lo, float hi) {
    ull r; asm("mov.b64 %0, {%1, %2};" : "=l"(r) : "f"(lo), "f"(hi)); return r;
}
__device__ __forceinline__ ull ffma2(ull a, ull b, ull c) {
    ull d; asm("fma.rn.f32x2 %0, %1, %2, %3;" : "=l"(d) : "l"(a), "l"(b), "l"(c)); return d;
}
__device__ __forceinline__ void unpack2(ull v, float& lo, float& hi) {
    asm("mov.b64 {%0, %1}, %2;" : "=f"(lo), "=f"(hi) : "l"(v));
}

// ---------------- gridbuild: hist + scan + scatter + T7v, ONE block ----------------
__global__ void __launch_bounds__(1024) gridbuild_kernel(const float* __restrict__ cloud,
                                                         const float* __restrict__ finw)
{
    __shared__ int scnt[GC];
    __shared__ int ssum[512];
    const int tid = threadIdx.x;

    for (int c = tid; c < GC; c += 1024) scnt[c] = 0;
    __syncthreads();

    for (int n = tid; n < NPTS; n += 1024) {
        float x = cloud[n * 3 + 0], y = cloud[n * 3 + 1], z = cloud[n * 3 + 2];
        d_pts4[n] = make_float4(x, y, z, x * x + y * y + z * z);
        int cx = min(G - 1, max(0, (int)(x * G)));
        int cy = min(G - 1, max(0, (int)(y * G)));
        int cz = min(G - 1, max(0, (int)(z * G)));
        int c = (cz * G + cy) * G + cx;
        d_ptCell[n] = c;
        atomicAdd(&scnt[c], 1);
    }
    __syncthreads();

    int c0 = 0, c1 = 0, c2 = 0, c3 = 0, s = 0;
    if (tid < 512) {
        if (4 * tid < GC) {
            c0 = scnt[4 * tid + 0]; c1 = scnt[4 * tid + 1];
            c2 = scnt[4 * tid + 2]; c3 = scnt[4 * tid + 3];
        }
        s = c0 + c1 + c2 + c3;
        ssum[tid] = s;
    }
    __syncthreads();
    for (int off = 1; off < 512; off <<= 1) {
        int v = 0;
        if (tid < 512 && tid >= off) v = ssum[tid - off];
        __syncthreads();
        if (tid < 512) ssum[tid] += v;
        __syncthreads();
    }
    if (tid < 512 && 4 * tid < GC) {
        int excl = ssum[tid] - s;
        d_cellStart[4 * tid + 0] = excl;
        d_cellStart[4 * tid + 1] = excl + c0;
        d_cellStart[4 * tid + 2] = excl + c0 + c1;
        d_cellStart[4 * tid + 3] = excl + c0 + c1 + c2;
        scnt[4 * tid + 0] = excl;
        scnt[4 * tid + 1] = excl + c0;
        scnt[4 * tid + 2] = excl + c0 + c1;
        scnt[4 * tid + 3] = excl + c0 + c1 + c2;
    }
    if (tid == 511) d_cellStart[GC] = ssum[511];
    __syncthreads();

    for (int n = tid; n < NPTS; n += 1024) {
        const int c = d_ptCell[n];
        const int pos = atomicAdd(&scnt[c], 1);
        d_spts[pos] = d_pts4[n];
        d_sidx[pos] = n;
        d_rank[n] = pos;
    }

    // T7v: finw [32,416] -> [104][32][4]
    for (int t = tid; t < 104 * 32 * 4; t += 1024) {
        int c4 = t >> 7, j = (t >> 2) & 31, q = t & 3;
        d_T7v[t] = finw[j * 416 + (c4 << 2) + q];
    }
}

// ---------------- KNN: one WARP per query, distributed top-16 + softmax ----------------
__device__ __forceinline__ void warp_scan_range(int st, int en, int lane,
                                                float qx, float qy, float qz,
                                                float& e, int& ei, float& thresh)
{
    const int nb = (en - st + 31) >> 5;
    for (int b = 0; b < nb; b++) {
        const int p = st + (b << 5) + lane;
        float dcand = INFINITY;
        if (p < en) {
            const float4 c = d_spts[p];
            const float dx = qx - c.x, dy = qy - c.y, dz = qz - c.z;
            dcand = fmaf(dx, dx, fmaf(dy, dy, dz * dz));
        }
        unsigned mask = __ballot_sync(FULLM, dcand <= thresh);
        while (mask) {
            const int src = __ffs(mask) - 1;
            mask &= mask - 1;
            const float v = __shfl_sync(FULLM, dcand, src);
            const int  vi = __shfl_sync(FULLM, p,     src);
            if (v <= thresh) {              // uniform
                const unsigned le = __ballot_sync(FULLM, e <= v) & 0xFFFFu;
                const int pos = __popc(le);
                const float pe = __shfl_up_sync(FULLM, e, 1);
                const int  pei = __shfl_up_sync(FULLM, ei, 1);
                if (lane > pos) { e = pe; ei = pei; }
                if (lane == pos) { e = v; ei = vi; }
                thresh = fminf(thresh, __shfl_sync(FULLM, e, 15));
            }
        }
    }
}

__global__ void __launch_bounds__(256) knn_warp_kernel()
{
    const int lane = threadIdx.x & 31;
    const int s = (blockIdx.x * 256 + threadIdx.x) >> 5;   // query = sorted position
    const float4 pq = d_spts[s];
    const int cx = min(G - 1, max(0, (int)(pq.x * G)));
    const int cy = min(G - 1, max(0, (int)(pq.y * G)));
    const int cz = min(G - 1, max(0, (int)(pq.z * G)));

    float e = INFINITY; int ei = 0;
    // seed thresh: provable upper bound on kd15 from 32 sorted-order neighbors
    float thresh;
    {
        const int base = min(max(s - 15, 0), NPTS - 32);
        const float4 c = d_spts[base + lane];
        const float dx = pq.x - c.x, dy = pq.y - c.y, dz = pq.z - c.z;
        float v = fmaf(dx, dx, fmaf(dy, dy, dz * dz));
        const int local = lane & 7;
        {
            float o; bool lower, asc;
            o = __shfl_xor_sync(FULLM, v, 1); lower = !(local & 1); asc = !(local & 2);
            v = (lower == asc) ? fminf(v, o) : fmaxf(v, o);
            o = __shfl_xor_sync(FULLM, v, 2); lower = !(local & 2); asc = !(local & 4);
            v = (lower == asc) ? fminf(v, o) : fmaxf(v, o);
            o = __shfl_xor_sync(FULLM, v, 1); lower = !(local & 1); asc = !(local & 4);
            v = (lower == asc) ? fminf(v, o) : fmaxf(v, o);
            o = __shfl_xor_sync(FULLM, v, 4); lower = !(local & 4);
            v = lower ? fminf(v, o) : fmaxf(v, o);
            o = __shfl_xor_sync(FULLM, v, 2); lower = !(local & 2);
            v = lower ? fminf(v, o) : fmaxf(v, o);
            o = __shfl_xor_sync(FULLM, v, 1); lower = !(local & 1);
            v = lower ? fminf(v, o) : fmaxf(v, o);
        }
        float m3 = __shfl_sync(FULLM, v, (lane & ~7) + 3);   // group's 4th smallest
        m3 = fmaxf(m3, __shfl_xor_sync(FULLM, m3, 8));
        m3 = fmaxf(m3, __shfl_xor_sync(FULLM, m3, 16));
        thresh = m3;
    }

    for (int m = 0; m < G; m++) {
        const int x0 = max(cx - m, 0), x1 = min(cx + m, G - 1);
        const int y0 = max(cy - m, 0), y1 = min(cy + m, G - 1);
        const int z0 = max(cz - m, 0), z1 = min(cz + m, G - 1);
        for (int z = z0; z <= z1; z++) {
            const bool zs = (z == cz - m) || (z == cz + m);
            for (int y = y0; y <= y1; y++) {
                const bool edge = zs || (y == cy - m) || (y == cy + m);
                const int rowc = (z * G + y) * G;
                if (edge) {
                    warp_scan_range(d_cellStart[rowc + x0], d_cellStart[rowc + x1 + 1],
                                    lane, pq.x, pq.y, pq.z, e, ei, thresh);
                } else {
                    if (cx - m >= 0)
                        warp_scan_range(d_cellStart[rowc + cx - m], d_cellStart[rowc + cx - m + 1],
                                        lane, pq.x, pq.y, pq.z, e, ei, thresh);
                    if (cx + m <= G - 1)
                        warp_scan_range(d_cellStart[rowc + cx + m], d_cellStart[rowc + cx + m + 1],
                                        lane, pq.x, pq.y, pq.z, e, ei, thresh);
                }
            }
        }
        const float bound = (float)m * HCELL;
        const float e15 = __shfl_sync(FULLM, e, 15);
        if (e15 < bound * bound) break;
    }

    // softmax of -sqrt(e) over lanes 0..15 (e sorted ascending -> max(-d) at lane 0)
    const float d = sqrtf(fmaxf(e, 1e-12f));
    const float d0 = __shfl_sync(FULLM, d, 0);
    float ex = (lane < KNN) ? expf(d0 - d) : 0.f;
    float ssum = ex;
    #pragma unroll
    for (int t = 8; t > 0; t >>= 1) ssum += __shfl_xor_sync(FULLM, ssum, t);

    if (lane < KNN) {
        d_knn[s * KNN + lane] = ei;          // sorted-space neighbor
        d_wgt[s * KNN + lane] = ex / ssum;
    }
}

// ---------------- fused MLP mega-kernel (f32x2 packed FMA) ----------------
#define PITCH  68
#define PITCH2 136
#define OFS_CF   0
#define OFS_BIG  (128 * PITCH)
#define OFS_BS   (384 * PITCH)
#define OFS_AS0  (OFS_BIG + 192 * PITCH)
#define SMEM_MLP ((384 * PITCH + 16 * PITCH2) * 4)

__device__ void mlp_layer(const float* __restrict__ As, int K, int k3pad,
                          const float* __restrict__ W, const float* __restrict__ bias,
                          int Nc, int act, float* Cs, float* gout,
                          const int* __restrict__ srank, float* Bs2)
{
    const int tid = threadIdx.x;
    const int tcol = tid & 15, trow = tid >> 4;
    for (int n0 = 0; n0 < Nc; n0 += 64) {
        ull acc2[2][4];
        #pragma unroll
        for (int p = 0; p < 2; p++)
            #pragma unroll
            for (int j = 0; j < 4; j++) acc2[p][j] = 0ULL;

        for (int k0 = 0; k0 < K; k0 += 16) {
            __syncthreads();
            if (k3pad) {
                for (int idx = tid; idx < 16 * 64; idx += 256) {
                    int k = idx >> 6, n = idx & 63;
                    float v = (k < 3) ? W[n * 3 + k] : 0.f;
                    Bs2[k * PITCH2 + 2 * n + 0] = v;
                    Bs2[k * PITCH2 + 2 * n + 1] = v;
                }
            } else {
                const int n = tid >> 2, kq = (tid & 3) << 2;
                const float4 w4 = *(const float4*)&W[(n0 + n) * K + k0 + kq];
                *(ull*)&Bs2[(kq + 0) * PITCH2 + 2 * n] = pack2(w4.x, w4.x);
                *(ull*)&Bs2[(kq + 1) * PITCH2 + 2 * n] = pack2(w4.y, w4.y);
                *(ull*)&Bs2[(kq + 2) * PITCH2 + 2 * n] = pack2(w4.z, w4.z);
                *(ull*)&Bs2[(kq + 3) * PITCH2 + 2 * n] = pack2(w4.w, w4.w);
            }
            __syncthreads();
            #pragma unroll
            for (int k = 0; k < 16; k++) {
                const float4 av = *(const float4*)&As[(k0 + k) * PITCH + (trow << 2)];
                const ull a01 = pack2(av.x, av.y);
                const ull a23 = pack2(av.z, av.w);
                const ulonglong2 b01 = *(const ulonglong2*)&Bs2[k * PITCH2 + (tcol << 3)];
                const ulonglong2 b23 = *(const ulonglong2*)&Bs2[k * PITCH2 + (tcol << 3) + 4];
                acc2[0][0] = ffma2(a01, b01.x, acc2[0][0]);
                acc2[0][1] = ffma2(a01, b01.y, acc2[0][1]);
                acc2[0][2] = ffma2(a01, b23.x, acc2[0][2]);
                acc2[0][3] = ffma2(a01, b23.y, acc2[0][3]);
                acc2[1][0] = ffma2(a23, b01.x, acc2[1][0]);
                acc2[1][1] = ffma2(a23, b01.y, acc2[1][1]);
                acc2[1][2] = ffma2(a23, b23.x, acc2[1][2]);
                acc2[1][3] = ffma2(a23, b23.y, acc2[1][3]);
            }
        }
        const float4 bb = *(const float4*)&bias[n0 + (tcol << 2)];
        const float bbr[4] = {bb.x, bb.y, bb.z, bb.w};
        #pragma unroll
        for (int i = 0; i < 4; i++) {
            float v[4];
            #pragma unroll
            for (int j = 0; j < 4; j++) {
                float lo, hi;
                unpack2(acc2[i >> 1][j], lo, hi);
                v[j] = ((i & 1) ? hi : lo) + bbr[j];
                if (act) v[j] = lrelu(v[j]);
            }
            const int lrow = (trow << 2) + i;
            if (gout) {
                float4 r; r.x = v[0]; r.y = v[1]; r.z = v[2]; r.w = v[3];
                *(float4*)&gout[srank[lrow] * 128 + n0 + (tcol << 2)] = r;
            }
            if (Cs) {
                #pragma unroll
                for (int j = 0; j < 4; j++)
                    Cs[(n0 + (tcol << 2) + j) * PITCH + lrow] = v[j];
            }
        }
    }
    __syncthreads();
}

__global__ void __launch_bounds__(256) mlp_kernel(
    const float* __restrict__ cloud, const float* __restrict__ img,
    const float* __restrict__ pc1w, const float* __restrict__ pc1b,
    const float* __restrict__ pc2w, const float* __restrict__ pc2b,
    const float* __restrict__ ps1w, const float* __restrict__ ps1b,
    const float* __restrict__ ps2w, const float* __restrict__ ps2b,
    const float* __restrict__ c1w,  const float* __restrict__ c1b,
    const float* __restrict__ c2w,  const float* __restrict__ c2b)
{
    extern __shared__ float smem[];
    __shared__ int srank[64];
    float* bufCf  = smem + OFS_CF;
    float* bufBig = smem + OFS_BIG;
    float* Bs2    = smem + OFS_BS;
    float* As0    = smem + OFS_AS0;
    const int tid = threadIdx.x;
    const int p0 = blockIdx.x * 64;

    if (tid < 64) srank[tid] = d_rank[p0 + tid];

    if (blockIdx.y == 0) {
        for (int idx = tid; idx < 16 * 64; idx += 256) {
            int k = idx >> 6, m = idx & 63;
            As0[k * PITCH + m] = (k < 3) ? cloud[(p0 + m) * 3 + k] : 0.f;
        }
        mlp_layer(As0,    16, 1, pc1w, pc1b,  64, 1, bufBig, nullptr, srank, Bs2);
        mlp_layer(bufBig, 64, 0, pc2w, pc2b, 128, 0, bufCf,  d_cf,    srank, Bs2);
        mlp_layer(bufCf, 128, 0, ps1w, ps1b, 256, 1, bufBig, nullptr, srank, Bs2);
        mlp_layer(bufBig,256, 0, ps2w, ps2b, 128, 0, nullptr, d_h,    srank, Bs2);
    } else {
        for (int idx = tid; idx < 32 * 64; idx += 256) {
            int k = idx >> 6, m = idx & 63;
            As0[k * PITCH + m] = img[k * NPTS + p0 + m];
        }
        mlp_layer(As0,    32, 0, c1w, c1b,  64, 1, bufBig, nullptr, srank, Bs2);
        mlp_layer(bufBig, 64, 0, c2w, c2b, 128, 0, nullptr, d_g,    srank, Bs2);
    }
}

// ---------------- final: sorted-order gather + weighted max-pool + block-coop GEMM ----------------
__global__ void __launch_bounds__(256) final_kernel(const float* __restrict__ img,
                                                    const float* __restrict__ fb,
                                                    float* __restrict__ out)
{
    __shared__ float swgt[8][KNN];
    __shared__ int   sidx[8][KNN];
    __shared__ float sfin[8][416];
    __shared__ float spart[8][8][32];   // [warp][point][outchan]
    const int w = threadIdx.x >> 5, lane = threadIdx.x & 31;
    const int s = blockIdx.x * 8 + w;   // sorted position
    const int orig = d_sidx[s];

    if (lane < KNN) {
        swgt[w][lane] = d_wgt[s * KNN + lane];
        sidx[w][lane] = d_knn[s * KNN + lane];
    }
    __syncwarp();

    float4 sf = make_float4(-INFINITY, -INFINITY, -INFINITY, -INFINITY);
    float4 sp = make_float4(-INFINITY, -INFINITY, -INFINITY, -INFINITY);
    #pragma unroll
    for (int k = 0; k < KNN; k++) {
        const int ik = sidx[w][k];
        const float wk = swgt[w][k];
        const float4 gv = *(const float4*)&d_g[ik * 128 + (lane << 2)];
        const float4 hv = *(const float4*)&d_h[ik * 128 + (lane << 2)];
        sf.x = fmaxf(sf.x, gv.x * wk); sf.y = fmaxf(sf.y, gv.y * wk);
        sf.z = fmaxf(sf.z, gv.z * wk); sf.w = fmaxf(sf.w, gv.w * wk);
        sp.x = fmaxf(sp.x, hv.x * wk); sp.y = fmaxf(sp.y, hv.y * wk);
        sp.z = fmaxf(sp.z, hv.z * wk); sp.w = fmaxf(sp.w, hv.w * wk);
    }
    const int c4 = lane << 2;
    sfin[w][c4 + 0] = lrelu(sp.x); sfin[w][c4 + 1] = lrelu(sp.y);
    sfin[w][c4 + 2] = lrelu(sp.z); sfin[w][c4 + 3] = lrelu(sp.w);
    sfin[w][128 + lane] = lrelu(img[lane * NPTS + orig]);
    sfin[w][160 + c4 + 0] = lrelu(sf.x); sfin[w][160 + c4 + 1] = lrelu(sf.y);
    sfin[w][160 + c4 + 2] = lrelu(sf.z); sfin[w][160 + c4 + 3] = lrelu(sf.w);
    const float4 cv = *(const float4*)&d_cf[s * 128 + c4];
    sfin[w][288 + c4 + 0] = lrelu(cv.x); sfin[w][288 + c4 + 1] = lrelu(cv.y);
    sfin[w][288 + c4 + 2] = lrelu(cv.z); sfin[w][288 + c4 + 3] = lrelu(cv.w);
    __syncthreads();

    {
        float acc[8];
        #pragma unroll
        for (int p = 0; p < 8; p++) acc[p] = 0.f;
        const int cq0 = w * 13;
        #pragma unroll
        for (int i = 0; i < 13; i++) {
            const int cq = cq0 + i;
            const float4 t = *(const float4*)&d_T7v[((cq << 5) + lane) << 2];
            #pragma unroll
            for (int p = 0; p < 8; p++) {
                const float4 f = *(const float4*)&sfin[p][cq << 2];
                acc[p] = fmaf(f.x, t.x, fmaf(f.y, t.y, fmaf(f.z, t.z, fmaf(f.w, t.w, acc[p]))));
            }
        }
        #pragma unroll
        for (int p = 0; p < 8; p++) spart[w][p][lane] = acc[p];
    }
    __syncthreads();

    {
        float acc = fb[lane];
        #pragma unroll
        for (int w2 = 0; w2 < 8; w2++) acc += spart[w2][w][lane];
        out[lane * NPTS + d_sidx[blockIdx.x * 8 + w]] = acc;
    }
}

// ---------------- launch ----------------
extern "C" void kernel_launch(void* const* d_in, const int* in_sizes, int n_in,
                              void* d_out, int out_size)
{
    const float* img   = (const float*)d_in[0];
    const float* cloud = (const float*)d_in[1];
    const float* c1w  = (const float*)d_in[2];  const float* c1b  = (const float*)d_in[3];
    const float* c2w  = (const float*)d_in[4];  const float* c2b  = (const float*)d_in[5];
    const float* ps1w = (const float*)d_in[6];  const float* ps1b = (const float*)d_in[7];
    const float* ps2w = (const float*)d_in[8];  const float* ps2b = (const float*)d_in[9];
    const float* pc1w = (const float*)d_in[10]; const float* pc1b = (const float*)d_in[11];
    const float* pc2w = (const float*)d_in[12]; const float* pc2b = (const float*)d_in[13];
    const float* finw = (const float*)d_in[14]; const float* finb = (const float*)d_in[15];
    float* out = (float*)d_out;

    static cudaStream_t s1 = nullptr;
    static cudaEvent_t evFork = nullptr, evJoin = nullptr;
    if (s1 == nullptr) {
        cudaStreamCreateWithFlags(&s1, cudaStreamNonBlocking);
        cudaEventCreateWithFlags(&evFork, cudaEventDisableTiming);
        cudaEventCreateWithFlags(&evJoin, cudaEventDisableTiming);
        cudaFuncSetAttribute(mlp_kernel, cudaFuncAttributeMaxDynamicSharedMemorySize, SMEM_MLP);
    }

    // main stream: gridbuild (produces d_rank) -> fork -> knn
    gridbuild_kernel<<<1, 1024>>>(cloud, finw);
    cudaEventRecord(evFork, 0);
    knn_warp_kernel<<<NPTS * 32 / 256, 256>>>();

    // side stream: fused 6-layer MLP (f32x2), needs d_rank from gridbuild
    cudaStreamWaitEvent(s1, evFork, 0);
    mlp_kernel<<<dim3(NPTS / 64, 2), 256, SMEM_MLP, s1>>>(
        cloud, img, pc1w, pc1b, pc2w, pc2b, ps1w, ps1b, ps2w, ps2b,
        c1w, c1b, c2w, c2b);
    cudaEventRecord(evJoin, s1);

    cudaStreamWaitEvent(0, evJoin, 0);
    final_kernel<<<NPTS / 8, 256>>>(img, finb, out);
}

// round 15
// speedup vs baseline: 1.8035x; 1.8035x over previous
#include <cuda_runtime.h>
#include <cuda_bf16.h>
#include <math.h>

#define NPTS 16384
#define KNN  16
#define G    12
#define GC   (G * G * G)     // 1728 cells, ~9.5 pts/cell
#define HCELL (1.0f / G)
#define FULLM 0xffffffffu

// ---------------- scratch (device globals, no allocations) ----------------
__device__ float4 d_pts4[NPTS];
__device__ float  d_T7v[104 * 32 * 4];   // (c4, j, q) <- finw[j][4*c4+q]
__device__ float  d_cf[NPTS * 128];
__device__ float  d_g [NPTS * 128];
__device__ float  d_h [NPTS * 128];
__device__ int    d_knn[NPTS * KNN];
__device__ float  d_wgt[NPTS * KNN];
__device__ int    d_cellStart[GC + 1];
__device__ int    d_ptCell[NPTS];
__device__ float4 d_spts[NPTS];
__device__ int    d_sidx[NPTS];

__device__ __forceinline__ float lrelu(float x) { return x > 0.f ? x : 0.01f * x; }

// ---------------- gridbuild: hist + scan + scatter + T7v, ONE block ----------------
__global__ void __launch_bounds__(1024) gridbuild_kernel(const float* __restrict__ cloud,
                                                         const float* __restrict__ finw)
{
    __shared__ int scnt[GC];
    __shared__ int ssum[512];
    const int tid = threadIdx.x;

    for (int c = tid; c < GC; c += 1024) scnt[c] = 0;
    __syncthreads();

    for (int n = tid; n < NPTS; n += 1024) {
        float x = cloud[n * 3 + 0], y = cloud[n * 3 + 1], z = cloud[n * 3 + 2];
        d_pts4[n] = make_float4(x, y, z, x * x + y * y + z * z);
        int cx = min(G - 1, max(0, (int)(x * G)));
        int cy = min(G - 1, max(0, (int)(y * G)));
        int cz = min(G - 1, max(0, (int)(z * G)));
        int c = (cz * G + cy) * G + cx;
        d_ptCell[n] = c;
        atomicAdd(&scnt[c], 1);
    }
    __syncthreads();

    int c0 = 0, c1 = 0, c2 = 0, c3 = 0, s = 0;
    if (tid < 512) {
        if (4 * tid < GC) {
            c0 = scnt[4 * tid + 0]; c1 = scnt[4 * tid + 1];
            c2 = scnt[4 * tid + 2]; c3 = scnt[4 * tid + 3];
        }
        s = c0 + c1 + c2 + c3;
        ssum[tid] = s;
    }
    __syncthreads();
    for (int off = 1; off < 512; off <<= 1) {
        int v = 0;
        if (tid < 512 && tid >= off) v = ssum[tid - off];
        __syncthreads();
        if (tid < 512) ssum[tid] += v;
        __syncthreads();
    }
    if (tid < 512 && 4 * tid < GC) {
        int excl = ssum[tid] - s;
        d_cellStart[4 * tid + 0] = excl;
        d_cellStart[4 * tid + 1] = excl + c0;
        d_cellStart[4 * tid + 2] = excl + c0 + c1;
        d_cellStart[4 * tid + 3] = excl + c0 + c1 + c2;
        scnt[4 * tid + 0] = excl;
        scnt[4 * tid + 1] = excl + c0;
        scnt[4 * tid + 2] = excl + c0 + c1;
        scnt[4 * tid + 3] = excl + c0 + c1 + c2;
    }
    if (tid == 511) d_cellStart[GC] = ssum[511];
    __syncthreads();

    for (int n = tid; n < NPTS; n += 1024) {
        const int c = d_ptCell[n];
        const int pos = atomicAdd(&scnt[c], 1);
        d_spts[pos] = d_pts4[n];
        d_sidx[pos] = n;
    }

    // T7v: finw [32,416] -> [104][32][4]
    for (int t = tid; t < 104 * 32 * 4; t += 1024) {
        int c4 = t >> 7, j = (t >> 2) & 31, q = t & 3;
        d_T7v[t] = finw[j * 416 + (c4 << 2) + q];
    }
}

// ---------------- KNN: one WARP per query, distributed top-16 + softmax ----------------
__device__ __forceinline__ void warp_scan_range(int st, int en, int lane,
                                                float qx, float qy, float qz,
                                                float& e, int& ei, float& thresh)
{
    const int nb = (en - st + 31) >> 5;
    for (int b = 0; b < nb; b++) {
        const int p = st + (b << 5) + lane;
        float dcand = INFINITY;
        if (p < en) {
            const float4 c = d_spts[p];
            const float dx = qx - c.x, dy = qy - c.y, dz = qz - c.z;
            dcand = fmaf(dx, dx, fmaf(dy, dy, dz * dz));
        }
        unsigned mask = __ballot_sync(FULLM, dcand <= thresh);
        while (mask) {
            const int src = __ffs(mask) - 1;
            mask &= mask - 1;
            const float v = __shfl_sync(FULLM, dcand, src);
            const int  vi = __shfl_sync(FULLM, p,     src);
            if (v <= thresh) {              // uniform
                const unsigned le = __ballot_sync(FULLM, e <= v) & 0xFFFFu;
                const int pos = __popc(le);
                const float pe = __shfl_up_sync(FULLM, e, 1);
                const int  pei = __shfl_up_sync(FULLM, ei, 1);
                if (lane > pos) { e = pe; ei = pei; }
                if (lane == pos) { e = v; ei = vi; }
                thresh = fminf(thresh, __shfl_sync(FULLM, e, 15));
            }
        }
    }
}

__global__ void __launch_bounds__(256) knn_warp_kernel()
{
    const int lane = threadIdx.x & 31;
    const int s = (blockIdx.x * 256 + threadIdx.x) >> 5;   // query = sorted position
    const float4 pq = d_spts[s];
    const int cx = min(G - 1, max(0, (int)(pq.x * G)));
    const int cy = min(G - 1, max(0, (int)(pq.y * G)));
    const int cz = min(G - 1, max(0, (int)(pq.z * G)));

    float e = INFINITY; int ei = 0;
    // seed thresh: provable upper bound on kd15 from 32 sorted-order neighbors
    float thresh;
    {
        const int base = min(max(s - 15, 0), NPTS - 32);
        const float4 c = d_spts[base + lane];
        const float dx = pq.x - c.x, dy = pq.y - c.y, dz = pq.z - c.z;
        float v = fmaf(dx, dx, fmaf(dy, dy, dz * dz));
        const int local = lane & 7;
        {
            float o; bool lower, asc;
            o = __shfl_xor_sync(FULLM, v, 1); lower = !(local & 1); asc = !(local & 2);
            v = (lower == asc) ? fminf(v, o) : fmaxf(v, o);
            o = __shfl_xor_sync(FULLM, v, 2); lower = !(local & 2); asc = !(local & 4);
            v = (lower == asc) ? fminf(v, o) : fmaxf(v, o);
            o = __shfl_xor_sync(FULLM, v, 1); lower = !(local & 1); asc = !(local & 4);
            v = (lower == asc) ? fminf(v, o) : fmaxf(v, o);
            o = __shfl_xor_sync(FULLM, v, 4); lower = !(local & 4);
            v = lower ? fminf(v, o) : fmaxf(v, o);
            o = __shfl_xor_sync(FULLM, v, 2); lower = !(local & 2);
            v = lower ? fminf(v, o) : fmaxf(v, o);
            o = __shfl_xor_sync(FULLM, v, 1); lower = !(local & 1);
            v = lower ? fminf(v, o) : fmaxf(v, o);
        }
        float m3 = __shfl_sync(FULLM, v, (lane & ~7) + 3);   // group's 4th smallest
        m3 = fmaxf(m3, __shfl_xor_sync(FULLM, m3, 8));
        m3 = fmaxf(m3, __shfl_xor_sync(FULLM, m3, 16));
        thresh = m3;
    }

    for (int m = 0; m < G; m++) {
        const int x0 = max(cx - m, 0), x1 = min(cx + m, G - 1);
        const int y0 = max(cy - m, 0), y1 = min(cy + m, G - 1);
        const int z0 = max(cz - m, 0), z1 = min(cz + m, G - 1);
        for (int z = z0; z <= z1; z++) {
            const bool zs = (z == cz - m) || (z == cz + m);
            for (int y = y0; y <= y1; y++) {
                const bool edge = zs || (y == cy - m) || (y == cy + m);
                const int rowc = (z * G + y) * G;
                if (edge) {
                    warp_scan_range(d_cellStart[rowc + x0], d_cellStart[rowc + x1 + 1],
                                    lane, pq.x, pq.y, pq.z, e, ei, thresh);
                } else {
                    if (cx - m >= 0)
                        warp_scan_range(d_cellStart[rowc + cx - m], d_cellStart[rowc + cx - m + 1],
                                        lane, pq.x, pq.y, pq.z, e, ei, thresh);
                    if (cx + m <= G - 1)
                        warp_scan_range(d_cellStart[rowc + cx + m], d_cellStart[rowc + cx + m + 1],
                                        lane, pq.x, pq.y, pq.z, e, ei, thresh);
                }
            }
        }
        const float bound = (float)m * HCELL;
        const float e15 = __shfl_sync(FULLM, e, 15);
        if (e15 < bound * bound) break;
    }

    // softmax of -sqrt(e) over lanes 0..15 (e sorted ascending -> max(-d) at lane 0)
    const float d = sqrtf(fmaxf(e, 1e-12f));
    const float d0 = __shfl_sync(FULLM, d, 0);
    float ex = (lane < KNN) ? expf(d0 - d) : 0.f;
    float ssum = ex;
    #pragma unroll
    for (int t = 8; t > 0; t >>= 1) ssum += __shfl_xor_sync(FULLM, ssum, t);

    if (lane < KNN) {
        const int orig = d_sidx[s];
        d_knn[orig * KNN + lane] = d_sidx[ei];
        d_wgt[orig * KNN + lane] = ex / ssum;
    }
}

// ---------------- MLP layers (R13-proven fp32 micro-kernel) ----------------
#define PITCH 68
// point-chain smem layout
#define OFS_CF   0
#define OFS_BIG  (128 * PITCH)
#define OFS_BS   (384 * PITCH)
#define OFS_AS0  (OFS_BIG + 192 * PITCH)
#define SMEM_PTS (400 * PITCH * 4)
// img-chain smem layout (small)
#define IOFS_AS0 0
#define IOFS_B64 (32 * PITCH)
#define IOFS_BS  (96 * PITCH)
#define SMEM_IMG (112 * PITCH * 4)

__device__ void mlp_layer(const float* __restrict__ As, int K, int k3pad,
                          const float* __restrict__ W, const float* __restrict__ bias,
                          int Nc, int act, float* Cs, float* gout, int m0, float* Bs)
{
    const int tid = threadIdx.x;
    const int tcol = tid & 15, trow = tid >> 4;
    for (int n0 = 0; n0 < Nc; n0 += 64) {
        float acc[4][4];
        #pragma unroll
        for (int i = 0; i < 4; i++)
            #pragma unroll
            for (int j = 0; j < 4; j++) acc[i][j] = 0.f;

        for (int k0 = 0; k0 < K; k0 += 16) {
            __syncthreads();
            if (k3pad) {
                for (int idx = tid; idx < 16 * 64; idx += 256) {
                    int k = idx >> 6, n = idx & 63;
                    Bs[k * PITCH + n] = (k < 3) ? W[n * 3 + k] : 0.f;
                }
            } else {
                const int n = tid >> 2, kq = (tid & 3) << 2;
                const float4 w4 = *(const float4*)&W[(n0 + n) * K + k0 + kq];
                Bs[(kq + 0) * PITCH + n] = w4.x;
                Bs[(kq + 1) * PITCH + n] = w4.y;
                Bs[(kq + 2) * PITCH + n] = w4.z;
                Bs[(kq + 3) * PITCH + n] = w4.w;
            }
            __syncthreads();
            #pragma unroll
            for (int k = 0; k < 16; k++) {
                const float4 av = *(const float4*)&As[(k0 + k) * PITCH + (trow << 2)];
                const float4 bv = *(const float4*)&Bs[k * PITCH + (tcol << 2)];
                const float ar[4] = {av.x, av.y, av.z, av.w};
                const float br[4] = {bv.x, bv.y, bv.z, bv.w};
                #pragma unroll
                for (int i = 0; i < 4; i++)
                    #pragma unroll
                    for (int j = 0; j < 4; j++)
                        acc[i][j] = fmaf(ar[i], br[j], acc[i][j]);
            }
        }
        const float4 bb = *(const float4*)&bias[n0 + (tcol << 2)];
        const float bbr[4] = {bb.x, bb.y, bb.z, bb.w};
        #pragma unroll
        for (int i = 0; i < 4; i++) {
            float v[4];
            #pragma unroll
            for (int j = 0; j < 4; j++) {
                v[j] = acc[i][j] + bbr[j];
                if (act) v[j] = lrelu(v[j]);
            }
            if (gout) {
                float4 r; r.x = v[0]; r.y = v[1]; r.z = v[2]; r.w = v[3];
                *(float4*)&gout[(m0 + (trow << 2) + i) * 128 + n0 + (tcol << 2)] = r;
            }
            if (Cs) {
                #pragma unroll
                for (int j = 0; j < 4; j++)
                    Cs[(n0 + (tcol << 2) + j) * PITCH + (trow << 2) + i] = v[j];
            }
        }
    }
    __syncthreads();
}

// point chain: pts(3) -> 64 (lrelu) -> cf(128) -> 256 (lrelu) -> h(128)
__global__ void __launch_bounds__(256) mlp_pts_kernel(
    const float* __restrict__ cloud,
    const float* __restrict__ pc1w, const float* __restrict__ pc1b,
    const float* __restrict__ pc2w, const float* __restrict__ pc2b,
    const float* __restrict__ ps1w, const float* __restrict__ ps1b,
    const float* __restrict__ ps2w, const float* __restrict__ ps2b)
{
    extern __shared__ float smem[];
    float* bufCf  = smem + OFS_CF;
    float* bufBig = smem + OFS_BIG;
    float* Bs     = smem + OFS_BS;
    float* As0    = smem + OFS_AS0;
    const int tid = threadIdx.x;
    const int p0 = blockIdx.x * 64;

    for (int idx = tid; idx < 16 * 64; idx += 256) {
        int k = idx >> 6, m = idx & 63;
        As0[k * PITCH + m] = (k < 3) ? cloud[(p0 + m) * 3 + k] : 0.f;
    }
    mlp_layer(As0,    16, 1, pc1w, pc1b,  64, 1, bufBig, nullptr, p0, Bs);
    mlp_layer(bufBig, 64, 0, pc2w, pc2b, 128, 0, bufCf,  d_cf,    p0, Bs);
    mlp_layer(bufCf, 128, 0, ps1w, ps1b, 256, 1, bufBig, nullptr, p0, Bs);
    mlp_layer(bufBig,256, 0, ps2w, ps2b, 128, 0, nullptr, d_h,    p0, Bs);
}

// img chain: imf(32) -> 64 (lrelu) -> g(128)
__global__ void __launch_bounds__(256) mlp_img_kernel(
    const float* __restrict__ img,
    const float* __restrict__ c1w, const float* __restrict__ c1b,
    const float* __restrict__ c2w, const float* __restrict__ c2b)
{
    extern __shared__ float smem[];
    float* As0  = smem + IOFS_AS0;
    float* b64  = smem + IOFS_B64;
    float* Bs   = smem + IOFS_BS;
    const int tid = threadIdx.x;
    const int p0 = blockIdx.x * 64;

    for (int idx = tid; idx < 32 * 64; idx += 256) {
        int k = idx >> 6, m = idx & 63;
        As0[k * PITCH + m] = img[k * NPTS + p0 + m];
    }
    mlp_layer(As0, 32, 0, c1w, c1b,  64, 1, b64, nullptr, p0, Bs);
    mlp_layer(b64, 64, 0, c2w, c2b, 128, 0, nullptr, d_g, p0, Bs);
}

// ---------------- final: gather + weighted max-pool + concat + block-coop GEMM ----------------
__global__ void __launch_bounds__(256) final_kernel(const float* __restrict__ img,
                                                    const float* __restrict__ fb,
                                                    float* __restrict__ out)
{
    __shared__ float swgt[8][KNN];
    __shared__ int   sidx[8][KNN];
    __shared__ float sfin[8][416];
    __shared__ float spart[8][8][32];   // [warp][point][outchan]
    const int w = threadIdx.x >> 5, lane = threadIdx.x & 31;
    const int n = blockIdx.x * 8 + w;

    if (lane < KNN) {
        swgt[w][lane] = d_wgt[n * KNN + lane];
        sidx[w][lane] = d_knn[n * KNN + lane];
    }
    __syncwarp();

    float4 sf = make_float4(-INFINITY, -INFINITY, -INFINITY, -INFINITY);
    float4 sp = make_float4(-INFINITY, -INFINITY, -INFINITY, -INFINITY);
    #pragma unroll
    for (int k = 0; k < KNN; k++) {
        const int ik = sidx[w][k];
        const float wk = swgt[w][k];
        const float4 gv = *(const float4*)&d_g[ik * 128 + (lane << 2)];
        const float4 hv = *(const float4*)&d_h[ik * 128 + (lane << 2)];
        sf.x = fmaxf(sf.x, gv.x * wk); sf.y = fmaxf(sf.y, gv.y * wk);
        sf.z = fmaxf(sf.z, gv.z * wk); sf.w = fmaxf(sf.w, gv.w * wk);
        sp.x = fmaxf(sp.x, hv.x * wk); sp.y = fmaxf(sp.y, hv.y * wk);
        sp.z = fmaxf(sp.z, hv.z * wk); sp.w = fmaxf(sp.w, hv.w * wk);
    }
    const int c4 = lane << 2;
    sfin[w][c4 + 0] = lrelu(sp.x); sfin[w][c4 + 1] = lrelu(sp.y);
    sfin[w][c4 + 2] = lrelu(sp.z); sfin[w][c4 + 3] = lrelu(sp.w);
    sfin[w][128 + lane] = lrelu(img[lane * NPTS + n]);
    sfin[w][160 + c4 + 0] = lrelu(sf.x); sfin[w][160 + c4 + 1] = lrelu(sf.y);
    sfin[w][160 + c4 + 2] = lrelu(sf.z); sfin[w][160 + c4 + 3] = lrelu(sf.w);
    const float4 cv = *(const float4*)&d_cf[n * 128 + c4];
    sfin[w][288 + c4 + 0] = lrelu(cv.x); sfin[w][288 + c4 + 1] = lrelu(cv.y);
    sfin[w][288 + c4 + 2] = lrelu(cv.z); sfin[w][288 + c4 + 3] = lrelu(cv.w);
    __syncthreads();

    // warp w covers c4-slice [13w, 13w+13) for ALL 8 points
    {
        float acc[8];
        #pragma unroll
        for (int p = 0; p < 8; p++) acc[p] = 0.f;
        const int cq0 = w * 13;
        #pragma unroll
        for (int i = 0; i < 13; i++) {
            const int cq = cq0 + i;
            const float4 t = *(const float4*)&d_T7v[((cq << 5) + lane) << 2];
            #pragma unroll
            for (int p = 0; p < 8; p++) {
                const float4 f = *(const float4*)&sfin[p][cq << 2];
                acc[p] = fmaf(f.x, t.x, fmaf(f.y, t.y, fmaf(f.z, t.z, fmaf(f.w, t.w, acc[p]))));
            }
        }
        #pragma unroll
        for (int p = 0; p < 8; p++) spart[w][p][lane] = acc[p];
    }
    __syncthreads();

    {
        float acc = fb[lane];
        #pragma unroll
        for (int w2 = 0; w2 < 8; w2++) acc += spart[w2][w][lane];
        out[lane * NPTS + blockIdx.x * 8 + w] = acc;
    }
}

// ---------------- launch ----------------
extern "C" void kernel_launch(void* const* d_in, const int* in_sizes, int n_in,
                              void* d_out, int out_size)
{
    const float* img   = (const float*)d_in[0];
    const float* cloud = (const float*)d_in[1];
    const float* c1w  = (const float*)d_in[2];  const float* c1b  = (const float*)d_in[3];
    const float* c2w  = (const float*)d_in[4];  const float* c2b  = (const float*)d_in[5];
    const float* ps1w = (const float*)d_in[6];  const float* ps1b = (const float*)d_in[7];
    const float* ps2w = (const float*)d_in[8];  const float* ps2b = (const float*)d_in[9];
    const float* pc1w = (const float*)d_in[10]; const float* pc1b = (const float*)d_in[11];
    const float* pc2w = (const float*)d_in[12]; const float* pc2b = (const float*)d_in[13];
    const float* finw = (const float*)d_in[14]; const float* finb = (const float*)d_in[15];
    float* out = (float*)d_out;

    static cudaStream_t s1 = nullptr;
    static cudaEvent_t evFork = nullptr, evJoin = nullptr;
    if (s1 == nullptr) {
        cudaStreamCreateWithFlags(&s1, cudaStreamNonBlocking);
        cudaEventCreateWithFlags(&evFork, cudaEventDisableTiming);
        cudaEventCreateWithFlags(&evJoin, cudaEventDisableTiming);
        cudaFuncSetAttribute(mlp_pts_kernel, cudaFuncAttributeMaxDynamicSharedMemorySize, SMEM_PTS);
        cudaFuncSetAttribute(mlp_img_kernel, cudaFuncAttributeMaxDynamicSharedMemorySize, SMEM_IMG);
    }

    // fork side stream at t=0 (point chain depends only on inputs)
    cudaEventRecord(evFork, 0);

    // main stream: gridbuild -> knn -> img chain
    gridbuild_kernel<<<1, 1024>>>(cloud, finw);
    knn_warp_kernel<<<NPTS * 32 / 256, 256>>>();
    mlp_img_kernel<<<NPTS / 64, 256, SMEM_IMG>>>(img, c1w, c1b, c2w, c2b);

    // side stream: heavy point chain (2.36 GF), overlaps the whole main path
    cudaStreamWaitEvent(s1, evFork, 0);
    mlp_pts_kernel<<<NPTS / 64, 256, SMEM_PTS, s1>>>(
        cloud, pc1w, pc1b, pc2w, pc2b, ps1w, ps1b, ps2w, ps2b);
    cudaEventRecord(evJoin, s1);

    // join, then final
    cudaStreamWaitEvent(0, evJoin, 0);
    final_kernel<<<NPTS / 8, 256>>>(img, finb, out);
}

// round 16
// speedup vs baseline: 1.9968x; 1.1072x over previous
#include <cuda_runtime.h>
#include <cuda_fp16.h>
#include <math.h>

#define NPTS 16384
#define KNN  16
#define G    12
#define GC   (G * G * G)     // 1728 cells, ~9.5 pts/cell
#define HCELL (1.0f / G)
#define FULLM 0xffffffffu

// ---------------- scratch (device globals, no allocations) ----------------
__device__ float4 d_pts4[NPTS];
__device__ float  d_T7v[104 * 32 * 4];   // (c4, j, q) <- finw[j][4*c4+q]
__device__ float  d_cf[NPTS * 128];
__device__ __half d_g [NPTS * 128];      // fp16 storage (gather traffic halved)
__device__ __half d_h [NPTS * 128];
__device__ int    d_knn[NPTS * KNN];
__device__ float  d_wgt[NPTS * KNN];
__device__ int    d_cellStart[GC + 1];
__device__ int    d_ptCell[NPTS];
__device__ float4 d_spts[NPTS];
__device__ int    d_sidx[NPTS];

__device__ __forceinline__ float lrelu(float x) { return x > 0.f ? x : 0.01f * x; }

// ---------------- gridbuild: hist + scan + scatter + T7v, ONE block ----------------
__global__ void __launch_bounds__(1024) gridbuild_kernel(const float* __restrict__ cloud,
                                                         const float* __restrict__ finw)
{
    __shared__ int scnt[GC];
    __shared__ int ssum[512];
    const int tid = threadIdx.x;

    for (int c = tid; c < GC; c += 1024) scnt[c] = 0;
    __syncthreads();

    for (int n = tid; n < NPTS; n += 1024) {
        float x = cloud[n * 3 + 0], y = cloud[n * 3 + 1], z = cloud[n * 3 + 2];
        d_pts4[n] = make_float4(x, y, z, x * x + y * y + z * z);
        int cx = min(G - 1, max(0, (int)(x * G)));
        int cy = min(G - 1, max(0, (int)(y * G)));
        int cz = min(G - 1, max(0, (int)(z * G)));
        int c = (cz * G + cy) * G + cx;
        d_ptCell[n] = c;
        atomicAdd(&scnt[c], 1);
    }
    __syncthreads();

    int c0 = 0, c1 = 0, c2 = 0, c3 = 0, s = 0;
    if (tid < 512) {
        if (4 * tid < GC) {
            c0 = scnt[4 * tid + 0]; c1 = scnt[4 * tid + 1];
            c2 = scnt[4 * tid + 2]; c3 = scnt[4 * tid + 3];
        }
        s = c0 + c1 + c2 + c3;
        ssum[tid] = s;
    }
    __syncthreads();
    for (int off = 1; off < 512; off <<= 1) {
        int v = 0;
        if (tid < 512 && tid >= off) v = ssum[tid - off];
        __syncthreads();
        if (tid < 512) ssum[tid] += v;
        __syncthreads();
    }
    if (tid < 512 && 4 * tid < GC) {
        int excl = ssum[tid] - s;
        d_cellStart[4 * tid + 0] = excl;
        d_cellStart[4 * tid + 1] = excl + c0;
        d_cellStart[4 * tid + 2] = excl + c0 + c1;
        d_cellStart[4 * tid + 3] = excl + c0 + c1 + c2;
        scnt[4 * tid + 0] = excl;
        scnt[4 * tid + 1] = excl + c0;
        scnt[4 * tid + 2] = excl + c0 + c1;
        scnt[4 * tid + 3] = excl + c0 + c1 + c2;
    }
    if (tid == 511) d_cellStart[GC] = ssum[511];
    __syncthreads();

    for (int n = tid; n < NPTS; n += 1024) {
        const int c = d_ptCell[n];
        const int pos = atomicAdd(&scnt[c], 1);
        d_spts[pos] = d_pts4[n];
        d_sidx[pos] = n;
    }

    for (int t = tid; t < 104 * 32 * 4; t += 1024) {
        int c4 = t >> 7, j = (t >> 2) & 31, q = t & 3;
        d_T7v[t] = finw[j * 416 + (c4 << 2) + q];
    }
}

// ---------------- KNN: one WARP per query, distributed top-16 + softmax ----------------
__device__ __forceinline__ void warp_scan_range(int st, int en, int lane,
                                                float qx, float qy, float qz,
                                                float& e, int& ei, float& thresh)
{
    const int nb = (en - st + 31) >> 5;
    for (int b = 0; b < nb; b++) {
        const int p = st + (b << 5) + lane;
        float dcand = INFINITY;
        if (p < en) {
            const float4 c = d_spts[p];
            const float dx = qx - c.x, dy = qy - c.y, dz = qz - c.z;
            dcand = fmaf(dx, dx, fmaf(dy, dy, dz * dz));
        }
        unsigned mask = __ballot_sync(FULLM, dcand <= thresh);
        while (mask) {
            const int src = __ffs(mask) - 1;
            mask &= mask - 1;
            const float v = __shfl_sync(FULLM, dcand, src);
            const int  vi = __shfl_sync(FULLM, p,     src);
            if (v <= thresh) {              // uniform
                const unsigned le = __ballot_sync(FULLM, e <= v) & 0xFFFFu;
                const int pos = __popc(le);
                const float pe = __shfl_up_sync(FULLM, e, 1);
                const int  pei = __shfl_up_sync(FULLM, ei, 1);
                if (lane > pos) { e = pe; ei = pei; }
                if (lane == pos) { e = v; ei = vi; }
                thresh = fminf(thresh, __shfl_sync(FULLM, e, 15));
            }
        }
    }
}

__global__ void __launch_bounds__(256) knn_warp_kernel()
{
    const int lane = threadIdx.x & 31;
    const int s = (blockIdx.x * 256 + threadIdx.x) >> 5;   // query = sorted position
    const float4 pq = d_spts[s];
    const int cx = min(G - 1, max(0, (int)(pq.x * G)));
    const int cy = min(G - 1, max(0, (int)(pq.y * G)));
    const int cz = min(G - 1, max(0, (int)(pq.z * G)));

    float e = INFINITY; int ei = 0;
    float thresh;
    {
        const int base = min(max(s - 15, 0), NPTS - 32);
        const float4 c = d_spts[base + lane];
        const float dx = pq.x - c.x, dy = pq.y - c.y, dz = pq.z - c.z;
        float v = fmaf(dx, dx, fmaf(dy, dy, dz * dz));
        const int local = lane & 7;
        {
            float o; bool lower, asc;
            o = __shfl_xor_sync(FULLM, v, 1); lower = !(local & 1); asc = !(local & 2);
            v = (lower == asc) ? fminf(v, o) : fmaxf(v, o);
            o = __shfl_xor_sync(FULLM, v, 2); lower = !(local & 2); asc = !(local & 4);
            v = (lower == asc) ? fminf(v, o) : fmaxf(v, o);
            o = __shfl_xor_sync(FULLM, v, 1); lower = !(local & 1); asc = !(local & 4);
            v = (lower == asc) ? fminf(v, o) : fmaxf(v, o);
            o = __shfl_xor_sync(FULLM, v, 4); lower = !(local & 4);
            v = lower ? fminf(v, o) : fmaxf(v, o);
            o = __shfl_xor_sync(FULLM, v, 2); lower = !(local & 2);
            v = lower ? fminf(v, o) : fmaxf(v, o);
            o = __shfl_xor_sync(FULLM, v, 1); lower = !(local & 1);
            v = lower ? fminf(v, o) : fmaxf(v, o);
        }
        float m3 = __shfl_sync(FULLM, v, (lane & ~7) + 3);
        m3 = fmaxf(m3, __shfl_xor_sync(FULLM, m3, 8));
        m3 = fmaxf(m3, __shfl_xor_sync(FULLM, m3, 16));
        thresh = m3;
    }

    for (int m = 0; m < G; m++) {
        const int x0 = max(cx - m, 0), x1 = min(cx + m, G - 1);
        const int y0 = max(cy - m, 0), y1 = min(cy + m, G - 1);
        const int z0 = max(cz - m, 0), z1 = min(cz + m, G - 1);
        for (int z = z0; z <= z1; z++) {
            const bool zs = (z == cz - m) || (z == cz + m);
            for (int y = y0; y <= y1; y++) {
                const bool edge = zs || (y == cy - m) || (y == cy + m);
                const int rowc = (z * G + y) * G;
                if (edge) {
                    warp_scan_range(d_cellStart[rowc + x0], d_cellStart[rowc + x1 + 1],
                                    lane, pq.x, pq.y, pq.z, e, ei, thresh);
                } else {
                    if (cx - m >= 0)
                        warp_scan_range(d_cellStart[rowc + cx - m], d_cellStart[rowc + cx - m + 1],
                                        lane, pq.x, pq.y, pq.z, e, ei, thresh);
                    if (cx + m <= G - 1)
                        warp_scan_range(d_cellStart[rowc + cx + m], d_cellStart[rowc + cx + m + 1],
                                        lane, pq.x, pq.y, pq.z, e, ei, thresh);
                }
            }
        }
        const float bound = (float)m * HCELL;
        const float e15 = __shfl_sync(FULLM, e, 15);
        if (e15 < bound * bound) break;
    }

    const float d = sqrtf(fmaxf(e, 1e-12f));
    const float d0 = __shfl_sync(FULLM, d, 0);
    float ex = (lane < KNN) ? expf(d0 - d) : 0.f;
    float ssum = ex;
    #pragma unroll
    for (int t = 8; t > 0; t >>= 1) ssum += __shfl_xor_sync(FULLM, ssum, t);

    if (lane < KNN) {
        const int orig = d_sidx[s];
        d_knn[orig * KNN + lane] = d_sidx[ei];
        d_wgt[orig * KNN + lane] = ex / ssum;
    }
}

// ---------------- fused MLP mega-kernel (K-tile 32, fp16 g/h outputs) ----------------
#define PITCH 68
#define OFS_CF   0
#define OFS_BIG  (128 * PITCH)
#define OFS_BS   (384 * PITCH)
#define OFS_AS0  (OFS_BIG + 192 * PITCH)
#define SMEM_MLP (416 * PITCH * 4)

template<int KT>
__device__ void mlp_layer(const float* __restrict__ As, int K, int k3pad,
                          const float* __restrict__ W, const float* __restrict__ bias,
                          int Nc, int act, float* Cs, float* fout, __half* hout,
                          int m0, float* Bs)
{
    const int tid = threadIdx.x;
    const int tcol = tid & 15, trow = tid >> 4;
    for (int n0 = 0; n0 < Nc; n0 += 64) {
        float acc[4][4];
        #pragma unroll
        for (int i = 0; i < 4; i++)
            #pragma unroll
            for (int j = 0; j < 4; j++) acc[i][j] = 0.f;

        for (int k0 = 0; k0 < K; k0 += KT) {
            __syncthreads();
            if (k3pad) {
                // K=16, only first 3 rows real
                for (int idx = tid; idx < 16 * 64; idx += 256) {
                    int k = idx >> 6, n = idx & 63;
                    Bs[k * PITCH + n] = (k < 3) ? W[n * 3 + k] : 0.f;
                }
            } else if (KT == 32) {
                const int n = tid >> 2, kq = (tid & 3) << 2;
                const float4 wa = *(const float4*)&W[(n0 + n) * K + k0 + kq];
                const float4 wb = *(const float4*)&W[(n0 + n) * K + k0 + kq + 16];
                Bs[(kq + 0) * PITCH + n] = wa.x;
                Bs[(kq + 1) * PITCH + n] = wa.y;
                Bs[(kq + 2) * PITCH + n] = wa.z;
                Bs[(kq + 3) * PITCH + n] = wa.w;
                Bs[(kq + 16) * PITCH + n] = wb.x;
                Bs[(kq + 17) * PITCH + n] = wb.y;
                Bs[(kq + 18) * PITCH + n] = wb.z;
                Bs[(kq + 19) * PITCH + n] = wb.w;
            } else {
                const int n = tid >> 2, kq = (tid & 3) << 2;
                const float4 w4 = *(const float4*)&W[(n0 + n) * K + k0 + kq];
                Bs[(kq + 0) * PITCH + n] = w4.x;
                Bs[(kq + 1) * PITCH + n] = w4.y;
                Bs[(kq + 2) * PITCH + n] = w4.z;
                Bs[(kq + 3) * PITCH + n] = w4.w;
            }
            __syncthreads();
            #pragma unroll
            for (int k = 0; k < KT; k++) {
                const float4 av = *(const float4*)&As[(k0 + k) * PITCH + (trow << 2)];
                const float4 bv = *(const float4*)&Bs[k * PITCH + (tcol << 2)];
                const float ar[4] = {av.x, av.y, av.z, av.w};
                const float br[4] = {bv.x, bv.y, bv.z, bv.w};
                #pragma unroll
                for (int i = 0; i < 4; i++)
                    #pragma unroll
                    for (int j = 0; j < 4; j++)
                        acc[i][j] = fmaf(ar[i], br[j], acc[i][j]);
            }
        }
        const float4 bb = *(const float4*)&bias[n0 + (tcol << 2)];
        const float bbr[4] = {bb.x, bb.y, bb.z, bb.w};
        #pragma unroll
        for (int i = 0; i < 4; i++) {
            float v[4];
            #pragma unroll
            for (int j = 0; j < 4; j++) {
                v[j] = acc[i][j] + bbr[j];
                if (act) v[j] = lrelu(v[j]);
            }
            const int lrow = (trow << 2) + i;
            if (fout) {
                float4 r; r.x = v[0]; r.y = v[1]; r.z = v[2]; r.w = v[3];
                *(float4*)&fout[(m0 + lrow) * 128 + n0 + (tcol << 2)] = r;
            }
            if (hout) {
                __half2 h01 = __floats2half2_rn(v[0], v[1]);
                __half2 h23 = __floats2half2_rn(v[2], v[3]);
                uint2 pk;
                pk.x = *(unsigned*)&h01;
                pk.y = *(unsigned*)&h23;
                *(uint2*)&hout[(m0 + lrow) * 128 + n0 + (tcol << 2)] = pk;
            }
            if (Cs) {
                #pragma unroll
                for (int j = 0; j < 4; j++)
                    Cs[(n0 + (tcol << 2) + j) * PITCH + lrow] = v[j];
            }
        }
    }
    __syncthreads();
}

__global__ void __launch_bounds__(256) mlp_kernel(
    const float* __restrict__ cloud, const float* __restrict__ img,
    const float* __restrict__ pc1w, const float* __restrict__ pc1b,
    const float* __restrict__ pc2w, const float* __restrict__ pc2b,
    const float* __restrict__ ps1w, const float* __restrict__ ps1b,
    const float* __restrict__ ps2w, const float* __restrict__ ps2b,
    const float* __restrict__ c1w,  const float* __restrict__ c1b,
    const float* __restrict__ c2w,  const float* __restrict__ c2b)
{
    extern __shared__ float smem[];
    float* bufCf  = smem + OFS_CF;
    float* bufBig = smem + OFS_BIG;
    float* Bs     = smem + OFS_BS;
    float* As0    = smem + OFS_AS0;
    const int tid = threadIdx.x;
    const int p0 = blockIdx.x * 64;

    if (blockIdx.y == 0) {
        // point chain: pts(3) -> 64 (lrelu) -> cf(128) -> 256 (lrelu) -> h(128)
        for (int idx = tid; idx < 16 * 64; idx += 256) {
            int k = idx >> 6, m = idx & 63;
            As0[k * PITCH + m] = (k < 3) ? cloud[(p0 + m) * 3 + k] : 0.f;
        }
        mlp_layer<16>(As0,    16, 1, pc1w, pc1b,  64, 1, bufBig, nullptr, nullptr, p0, Bs);
        mlp_layer<32>(bufBig, 64, 0, pc2w, pc2b, 128, 0, bufCf,  d_cf,    nullptr, p0, Bs);
        mlp_layer<32>(bufCf, 128, 0, ps1w, ps1b, 256, 1, bufBig, nullptr, nullptr, p0, Bs);
        mlp_layer<32>(bufBig,256, 0, ps2w, ps2b, 128, 0, nullptr, nullptr, d_h,    p0, Bs);
    } else {
        // img chain: imf(32) -> 64 (lrelu) -> g(128)
        for (int idx = tid; idx < 32 * 64; idx += 256) {
            int k = idx >> 6, m = idx & 63;
            As0[k * PITCH + m] = img[k * NPTS + p0 + m];
        }
        mlp_layer<32>(As0,    32, 0, c1w, c1b,  64, 1, bufBig, nullptr, nullptr, p0, Bs);
        mlp_layer<32>(bufBig, 64, 0, c2w, c2b, 128, 0, nullptr, nullptr, d_g,    p0, Bs);
    }
}

// ---------------- final: fp16 gather + weighted max-pool + concat + block-coop GEMM ----------------
__global__ void __launch_bounds__(256) final_kernel(const float* __restrict__ img,
                                                    const float* __restrict__ fb,
                                                    float* __restrict__ out)
{
    __shared__ float swgt[8][KNN];
    __shared__ int   sidx[8][KNN];
    __shared__ float sfin[8][416];
    __shared__ float spart[8][8][32];
    const int w = threadIdx.x >> 5, lane = threadIdx.x & 31;
    const int n = blockIdx.x * 8 + w;

    if (lane < KNN) {
        swgt[w][lane] = d_wgt[n * KNN + lane];
        sidx[w][lane] = d_knn[n * KNN + lane];
    }
    __syncwarp();

    float4 sf = make_float4(-INFINITY, -INFINITY, -INFINITY, -INFINITY);
    float4 sp = make_float4(-INFINITY, -INFINITY, -INFINITY, -INFINITY);
    #pragma unroll
    for (int k = 0; k < KNN; k++) {
        const int ik = sidx[w][k];
        const float wk = swgt[w][k];
        const uint2 gu = *(const uint2*)&d_g[ik * 128 + (lane << 2)];
        const uint2 hu = *(const uint2*)&d_h[ik * 128 + (lane << 2)];
        const float2 g01 = __half22float2(*(const __half2*)&gu.x);
        const float2 g23 = __half22float2(*(const __half2*)&gu.y);
        const float2 h01 = __half22float2(*(const __half2*)&hu.x);
        const float2 h23 = __half22float2(*(const __half2*)&hu.y);
        sf.x = fmaxf(sf.x, g01.x * wk); sf.y = fmaxf(sf.y, g01.y * wk);
        sf.z = fmaxf(sf.z, g23.x * wk); sf.w = fmaxf(sf.w, g23.y * wk);
        sp.x = fmaxf(sp.x, h01.x * wk); sp.y = fmaxf(sp.y, h01.y * wk);
        sp.z = fmaxf(sp.z, h23.x * wk); sp.w = fmaxf(sp.w, h23.y * wk);
    }
    const int c4 = lane << 2;
    sfin[w][c4 + 0] = lrelu(sp.x); sfin[w][c4 + 1] = lrelu(sp.y);
    sfin[w][c4 + 2] = lrelu(sp.z); sfin[w][c4 + 3] = lrelu(sp.w);
    sfin[w][128 + lane] = lrelu(img[lane * NPTS + n]);
    sfin[w][160 + c4 + 0] = lrelu(sf.x); sfin[w][160 + c4 + 1] = lrelu(sf.y);
    sfin[w][160 + c4 + 2] = lrelu(sf.z); sfin[w][160 + c4 + 3] = lrelu(sf.w);
    const float4 cv = *(const float4*)&d_cf[n * 128 + c4];
    sfin[w][288 + c4 + 0] = lrelu(cv.x); sfin[w][288 + c4 + 1] = lrelu(cv.y);
    sfin[w][288 + c4 + 2] = lrelu(cv.z); sfin[w][288 + c4 + 3] = lrelu(cv.w);
    __syncthreads();

    // warp w covers c4-slice [13w, 13w+13) for ALL 8 points
    {
        float acc[8];
        #pragma unroll
        for (int p = 0; p < 8; p++) acc[p] = 0.f;
        const int cq0 = w * 13;
        #pragma unroll
        for (int i = 0; i < 13; i++) {
            const int cq = cq0 + i;
            const float4 t = *(const float4*)&d_T7v[((cq << 5) + lane) << 2];
            #pragma unroll
            for (int p = 0; p < 8; p++) {
                const float4 f = *(const float4*)&sfin[p][cq << 2];
                acc[p] = fmaf(f.x, t.x, fmaf(f.y, t.y, fmaf(f.z, t.z, fmaf(f.w, t.w, acc[p]))));
            }
        }
        #pragma unroll
        for (int p = 0; p < 8; p++) spart[w][p][lane] = acc[p];
    }
    __syncthreads();

    {
        float acc = fb[lane];
        #pragma unroll
        for (int w2 = 0; w2 < 8; w2++) acc += spart[w2][w][lane];
        out[lane * NPTS + blockIdx.x * 8 + w] = acc;
    }
}

// ---------------- launch ----------------
extern "C" void kernel_launch(void* const* d_in, const int* in_sizes, int n_in,
                              void* d_out, int out_size)
{
    const float* img   = (const float*)d_in[0];
    const float* cloud = (const float*)d_in[1];
    const float* c1w  = (const float*)d_in[2];  const float* c1b  = (const float*)d_in[3];
    const float* c2w  = (const float*)d_in[4];  const float* c2b  = (const float*)d_in[5];
    const float* ps1w = (const float*)d_in[6];  const float* ps1b = (const float*)d_in[7];
    const float* ps2w = (const float*)d_in[8];  const float* ps2b = (const float*)d_in[9];
    const float* pc1w = (const float*)d_in[10]; const float* pc1b = (const float*)d_in[11];
    const float* pc2w = (const float*)d_in[12]; const float* pc2b = (const float*)d_in[13];
    const float* finw = (const float*)d_in[14]; const float* finb = (const float*)d_in[15];
    float* out = (float*)d_out;

    static cudaStream_t s1 = nullptr;
    static cudaEvent_t evFork = nullptr, evJoin = nullptr;
    if (s1 == nullptr) {
        cudaStreamCreateWithFlags(&s1, cudaStreamNonBlocking);
        cudaEventCreateWithFlags(&evFork, cudaEventDisableTiming);
        cudaEventCreateWithFlags(&evJoin, cudaEventDisableTiming);
        cudaFuncSetAttribute(mlp_kernel, cudaFuncAttributeMaxDynamicSharedMemorySize, SMEM_MLP);
    }

    cudaEventRecord(evFork, 0);

    // main stream: gridbuild -> knn
    gridbuild_kernel<<<1, 1024>>>(cloud, finw);
    knn_warp_kernel<<<NPTS * 32 / 256, 256>>>();

    // side stream: fused 6-layer MLP (point chain + img chain)
    cudaStreamWaitEvent(s1, evFork, 0);
    mlp_kernel<<<dim3(NPTS / 64, 2), 256, SMEM_MLP, s1>>>(
        cloud, img, pc1w, pc1b, pc2w, pc2b, ps1w, ps1b, ps2w, ps2b,
        c1w, c1b, c2w, c2b);
    cudaEventRecord(evJoin, s1);

    cudaStreamWaitEvent(0, evJoin, 0);
    final_kernel<<<NPTS / 8, 256>>>(img, finb, out);
}